// round 1
// baseline (speedup 1.0000x reference)
#include <cuda_runtime.h>

#define DD   32          // embedding dim D
#define MM   32          // memories per hop
#define LEAKY 0.2f

// scratch: Rh[slot*D + d], slot in [0, H*B*M); sized for 131072 slots * 32
__device__ float g_Rh[131072 * 32];
// winner[item] = max batch index b mapping to that item (last-wins scatter)
__device__ int g_winner[1 << 17];

__device__ __forceinline__ float warpSum(float v) {
    #pragma unroll
    for (int off = 16; off; off >>= 1) v += __shfl_xor_sync(0xffffffffu, v, off);
    return v;
}
__device__ __forceinline__ float warpMax(float v) {
    #pragma unroll
    for (int off = 16; off; off >>= 1) v = fmaxf(v, __shfl_xor_sync(0xffffffffu, v, off));
    return v;
}

// ---------------------------------------------------------------------------
// h_all / t_all gather. tid < HBM*8 -> h float4s ; else -> t float4s (leaky).
// ---------------------------------------------------------------------------
__global__ void gather_ht_kernel(const int* __restrict__ mh,
                                 const int* __restrict__ mt,
                                 const float4* __restrict__ ent,
                                 float4* __restrict__ out_h,
                                 float4* __restrict__ out_t,
                                 int HBM) {
    int tid = blockIdx.x * blockDim.x + threadIdx.x;
    int N = HBM * 8;                       // 8 float4 per 32-float row
    if (tid < N) {
        int slot = tid >> 3, j = tid & 7;
        int e = __ldg(&mh[slot]);
        out_h[slot * 8 + j] = ent[(size_t)e * 8 + j];
    } else if (tid < 2 * N) {
        int t2 = tid - N;
        int slot = t2 >> 3, j = t2 & 7;
        int e = __ldg(&mt[slot]);
        float4 v = ent[(size_t)e * 8 + j];
        v.x = v.x > 0.f ? v.x : LEAKY * v.x;
        v.y = v.y > 0.f ? v.y : LEAKY * v.y;
        v.z = v.z > 0.f ? v.z : LEAKY * v.z;
        v.w = v.w > 0.f ? v.w : LEAKY * v.w;
        out_t[slot * 8 + j] = v;
    }
}

// ---------------------------------------------------------------------------
// r_all gather (one block = one slot = one 4KB relation row) + fused Rh = R@h.
// Row is staged in shared so the Rh matvec reads L1/smem, not L2 again.
// ---------------------------------------------------------------------------
__global__ void gather_r_rh_kernel(const int* __restrict__ mr,
                                   const int* __restrict__ mh,
                                   const float4* __restrict__ rel,   // [REL, 256] as float4
                                   const float* __restrict__ ent,
                                   float4* __restrict__ out_r) {
    __shared__ float sR[DD * DD];   // 4KB
    __shared__ float sh[DD];
    int slot = blockIdx.x;
    int r = __ldg(&mr[slot]);
    float4 v = rel[(size_t)r * 256 + threadIdx.x];
    ((float4*)sR)[threadIdx.x] = v;
    out_r[(size_t)slot * 256 + threadIdx.x] = v;
    if (threadIdx.x < DD) {
        int e = __ldg(&mh[slot]);
        sh[threadIdx.x] = ent[(size_t)e * DD + threadIdx.x];
    }
    __syncthreads();
    if (threadIdx.x < DD) {
        int d = threadIdx.x;
        float acc = 0.f;
        #pragma unroll
        for (int e = 0; e < DD; e++) {
            int ee = (e + d) & (DD - 1);           // conflict-free rotation
            acc = fmaf(sR[d * DD + ee], sh[ee], acc);
        }
        g_Rh[(size_t)slot * DD + d] = acc;
    }
}

// ---------------------------------------------------------------------------
// last-wins scatter resolution
// ---------------------------------------------------------------------------
__global__ void reset_winner_kernel(const int* __restrict__ pos, int B) {
    int b = blockIdx.x * blockDim.x + threadIdx.x;
    if (b < B) g_winner[pos[b]] = -1;
}
__global__ void vote_winner_kernel(const int* __restrict__ pos, int B) {
    int b = blockIdx.x * blockDim.x + threadIdx.x;
    if (b < B) atomicMax(&g_winner[pos[b]], b);
}

// ---------------------------------------------------------------------------
// Hop loop: one warp per batch row b. lane = embedding dim d (= also m for
// softmax). Reads precomputed Rh + t_all (already in out), writes winning
// rows into iEmbed_new region of out.
// ---------------------------------------------------------------------------
__global__ void ripple_kernel(const int* __restrict__ pos,
                              const float* __restrict__ iE,
                              const float* __restrict__ t_all,
                              const float* __restrict__ W,
                              float* __restrict__ out_i,
                              int B, int nhop) {
    __shared__ float sW[DD * DD];
    for (int i = threadIdx.x; i < DD * DD; i += blockDim.x) sW[i] = W[i];
    __syncthreads();
    int warp = threadIdx.x >> 5, lane = threadIdx.x & 31;
    int b = blockIdx.x * (blockDim.x >> 5) + warp;
    if (b >= B) return;
    int p = pos[b];
    float item = iE[(size_t)p * DD + lane];

    for (int hop = 0; hop < nhop; hop++) {
        const float* Rh = g_Rh + (size_t)(hop * B + b) * MM * DD;
        const float* tb = t_all + (size_t)(hop * B + b) * MM * DD;
        // logits[m] = sum_d Rh[m][d] * item[d]; kept on lane == m
        float myLogit = 0.f;
        #pragma unroll
        for (int m = 0; m < MM; m++) {
            float v = warpSum(Rh[m * DD + lane] * item);
            if (m == lane) myLogit = v;
        }
        // softmax across lanes (m)
        float mx = warpMax(myLogit);
        float ex = expf(myLogit - mx);
        float s = warpSum(ex);
        float prob = ex / s;
        // o[d] = sum_m prob[m] * t[m][d]
        float o = 0.f;
        #pragma unroll
        for (int m = 0; m < MM; m++) {
            float pm = __shfl_sync(0xffffffffu, prob, m);
            o = fmaf(pm, tb[m * DD + lane], o);
        }
        // item = (item + o) @ W.T  ->  out[d] = sum_e x[e] * W[d][e]
        float x = item + o;
        float ni = 0.f;
        #pragma unroll
        for (int e = 0; e < DD; e++) {
            int ee = (e + lane) & (DD - 1);
            ni = fmaf(__shfl_sync(0xffffffffu, x, ee), sW[lane * DD + ee], ni);
        }
        item = ni;
    }
    if (g_winner[p] == b)
        out_i[(size_t)p * DD + lane] = item;
}

// ---------------------------------------------------------------------------
extern "C" void kernel_launch(void* const* d_in, const int* in_sizes, int n_in,
                              void* d_out, int out_size) {
    const int*   pos = (const int*)d_in[0];
    const int*   mh  = (const int*)d_in[1];
    const int*   mr  = (const int*)d_in[2];
    const int*   mt  = (const int*)d_in[3];
    const float* uE  = (const float*)d_in[4];
    const float* iE  = (const float*)d_in[5];
    const float* ent = (const float*)d_in[6];
    const float* rel = (const float*)d_in[7];
    const float* W   = (const float*)d_in[8];
    float* out = (float*)d_out;

    const int B   = in_sizes[0];              // 2048
    const int HBM = in_sizes[1];              // H*B*M = 131072
    const int nhop = HBM / (B * MM);          // 2
    const size_t Ue = (size_t)in_sizes[4];    // USER*D
    const size_t Ie = (size_t)in_sizes[5];    // ITEM*D

    float* out_u = out;
    float* out_i = out_u + Ue;
    float* out_h = out_i + Ie;
    float* out_t = out_h + (size_t)HBM * DD;
    float* out_r = out_t + (size_t)HBM * DD;

    // unchanged uEmbed + base copy of iEmbed (scatter overwrites rows later)
    cudaMemcpyAsync(out_u, uE, Ue * sizeof(float), cudaMemcpyDeviceToDevice);
    cudaMemcpyAsync(out_i, iE, Ie * sizeof(float), cudaMemcpyDeviceToDevice);

    // h_all / t_all
    {
        int total = 2 * HBM * 8;
        gather_ht_kernel<<<(total + 255) / 256, 256>>>(
            mh, mt, (const float4*)ent, (float4*)out_h, (float4*)out_t, HBM);
    }
    // r_all + fused Rh
    gather_r_rh_kernel<<<HBM, 256>>>(mr, mh, (const float4*)rel, ent, (float4*)out_r);

    // last-wins scatter resolution
    reset_winner_kernel<<<(B + 255) / 256, 256>>>(pos, B);
    vote_winner_kernel<<<(B + 255) / 256, 256>>>(pos, B);

    // hop computation + scatter (8 warps per block)
    ripple_kernel<<<(B + 7) / 8, 256>>>(pos, iE, out_t, W, out_i, B, nhop);
}

// round 2
// speedup vs baseline: 1.5524x; 1.5524x over previous
#include <cuda_runtime.h>

#define DD   32          // embedding dim D
#define MM   32          // memories per hop
#define LEAKY 0.2f

// scratch: Rh[slot*D + d], slot in [0, H*B*M); sized for 131072 slots * 32
__device__ float g_Rh[131072 * 32];
// winner[item] = max batch index b mapping to that item (last-wins scatter)
__device__ int g_winner[1 << 17];

__device__ __forceinline__ float warpSum(float v) {
    #pragma unroll
    for (int off = 16; off; off >>= 1) v += __shfl_xor_sync(0xffffffffu, v, off);
    return v;
}
__device__ __forceinline__ float warpMax(float v) {
    #pragma unroll
    for (int off = 16; off; off >>= 1) v = fmaxf(v, __shfl_xor_sync(0xffffffffu, v, off));
    return v;
}

// ---------------------------------------------------------------------------
// h_all / t_all gather. tid < HBM*8 -> h float4s ; else -> t float4s (leaky).
// ---------------------------------------------------------------------------
__global__ void gather_ht_kernel(const int* __restrict__ mh,
                                 const int* __restrict__ mt,
                                 const float4* __restrict__ ent,
                                 float4* __restrict__ out_h,
                                 float4* __restrict__ out_t,
                                 int HBM) {
    int tid = blockIdx.x * blockDim.x + threadIdx.x;
    int N = HBM * 8;                       // 8 float4 per 32-float row
    if (tid < N) {
        int slot = tid >> 3, j = tid & 7;
        int e = __ldg(&mh[slot]);
        __stcs(&out_h[slot * 8 + j], ent[(size_t)e * 8 + j]);
    } else if (tid < 2 * N) {
        int t2 = tid - N;
        int slot = t2 >> 3, j = t2 & 7;
        int e = __ldg(&mt[slot]);
        float4 v = ent[(size_t)e * 8 + j];
        v.x = v.x > 0.f ? v.x : LEAKY * v.x;
        v.y = v.y > 0.f ? v.y : LEAKY * v.y;
        v.z = v.z > 0.f ? v.z : LEAKY * v.z;
        v.w = v.w > 0.f ? v.w : LEAKY * v.w;
        out_t[slot * 8 + j] = v;           // re-read by ripple: keep cacheable
    }
}

// ---------------------------------------------------------------------------
// r_all gather + fused Rh = R@h.  ONE WARP PER SLOT, no block barrier.
// 8 independent LDG.128 per lane (MLP), streamed to gmem with evict-first
// (rel table stays L2-hot) and staged in smem for the Rh mat-vec.
// ---------------------------------------------------------------------------
__global__ void __launch_bounds__(256) gather_r_rh_kernel(
        const int* __restrict__ mr,
        const int* __restrict__ mh,
        const float4* __restrict__ rel,   // [REL, 256] as float4
        const float* __restrict__ ent,
        float4* __restrict__ out_r,
        int HBM) {
    __shared__ float4 sR4[8][256];        // 4KB per warp, 32KB per block
    int warp = threadIdx.x >> 5, lane = threadIdx.x & 31;
    int slot = blockIdx.x * 8 + warp;
    if (slot >= HBM) return;

    int r = __ldg(&mr[slot]);
    const float4* src = rel + (size_t)r * 256;
    float4* dst = out_r + (size_t)slot * 256;
    float4* s = sR4[warp];

    float4 v[8];
    #pragma unroll
    for (int k = 0; k < 8; k++)           // 8 outstanding L2 loads per lane
        v[k] = __ldg(&src[k * 32 + lane]);

    int e = __ldg(&mh[slot]);
    float hval = __ldg(&ent[(size_t)e * DD + lane]);

    #pragma unroll
    for (int k = 0; k < 8; k++) {
        __stcs(&dst[k * 32 + lane], v[k]); // streaming: never re-read
        s[k * 32 + lane] = v[k];
    }
    __syncwarp();

    const float* sR = (const float*)s;
    float acc = 0.f;
    #pragma unroll
    for (int i = 0; i < DD; i++) {
        int ee = (i + lane) & (DD - 1);    // conflict-free rotation
        acc = fmaf(sR[lane * DD + ee],
                   __shfl_sync(0xffffffffu, hval, ee), acc);
    }
    g_Rh[(size_t)slot * DD + lane] = acc;
}

// ---------------------------------------------------------------------------
// last-wins scatter resolution
// ---------------------------------------------------------------------------
__global__ void reset_winner_kernel(const int* __restrict__ pos, int B) {
    int b = blockIdx.x * blockDim.x + threadIdx.x;
    if (b < B) g_winner[pos[b]] = -1;
}
__global__ void vote_winner_kernel(const int* __restrict__ pos, int B) {
    int b = blockIdx.x * blockDim.x + threadIdx.x;
    if (b < B) atomicMax(&g_winner[pos[b]], b);
}

// ---------------------------------------------------------------------------
// Hop loop: one warp per batch row b. lane = embedding dim d (= also m for
// softmax). Reads precomputed Rh + t_all (already in out), writes winning
// rows into iEmbed_new region of out.
// ---------------------------------------------------------------------------
__global__ void ripple_kernel(const int* __restrict__ pos,
                              const float* __restrict__ iE,
                              const float* __restrict__ t_all,
                              const float* __restrict__ W,
                              float* __restrict__ out_i,
                              int B, int nhop) {
    __shared__ float sW[DD * DD];
    for (int i = threadIdx.x; i < DD * DD; i += blockDim.x) sW[i] = W[i];
    __syncthreads();
    int warp = threadIdx.x >> 5, lane = threadIdx.x & 31;
    int b = blockIdx.x * (blockDim.x >> 5) + warp;
    if (b >= B) return;
    int p = pos[b];
    float item = iE[(size_t)p * DD + lane];

    for (int hop = 0; hop < nhop; hop++) {
        const float* Rh = g_Rh + (size_t)(hop * B + b) * MM * DD;
        const float* tb = t_all + (size_t)(hop * B + b) * MM * DD;
        // logits[m] = sum_d Rh[m][d] * item[d]; kept on lane == m
        float myLogit = 0.f;
        #pragma unroll
        for (int m = 0; m < MM; m++) {
            float v = warpSum(Rh[m * DD + lane] * item);
            if (m == lane) myLogit = v;
        }
        // softmax across lanes (m)
        float mx = warpMax(myLogit);
        float ex = expf(myLogit - mx);
        float s = warpSum(ex);
        float prob = ex / s;
        // o[d] = sum_m prob[m] * t[m][d]
        float o = 0.f;
        #pragma unroll
        for (int m = 0; m < MM; m++) {
            float pm = __shfl_sync(0xffffffffu, prob, m);
            o = fmaf(pm, tb[m * DD + lane], o);
        }
        // item = (item + o) @ W.T  ->  out[d] = sum_e x[e] * W[d][e]
        float x = item + o;
        float ni = 0.f;
        #pragma unroll
        for (int e = 0; e < DD; e++) {
            int ee = (e + lane) & (DD - 1);
            ni = fmaf(__shfl_sync(0xffffffffu, x, ee), sW[lane * DD + ee], ni);
        }
        item = ni;
    }
    if (g_winner[p] == b)
        out_i[(size_t)p * DD + lane] = item;
}

// ---------------------------------------------------------------------------
extern "C" void kernel_launch(void* const* d_in, const int* in_sizes, int n_in,
                              void* d_out, int out_size) {
    const int*   pos = (const int*)d_in[0];
    const int*   mh  = (const int*)d_in[1];
    const int*   mr  = (const int*)d_in[2];
    const int*   mt  = (const int*)d_in[3];
    const float* uE  = (const float*)d_in[4];
    const float* iE  = (const float*)d_in[5];
    const float* ent = (const float*)d_in[6];
    const float* rel = (const float*)d_in[7];
    const float* W   = (const float*)d_in[8];
    float* out = (float*)d_out;

    const int B   = in_sizes[0];              // 2048
    const int HBM = in_sizes[1];              // H*B*M = 131072
    const int nhop = HBM / (B * MM);          // 2
    const size_t Ue = (size_t)in_sizes[4];    // USER*D
    const size_t Ie = (size_t)in_sizes[5];    // ITEM*D

    float* out_u = out;
    float* out_i = out_u + Ue;
    float* out_h = out_i + Ie;
    float* out_t = out_h + (size_t)HBM * DD;
    float* out_r = out_t + (size_t)HBM * DD;

    // unchanged uEmbed + base copy of iEmbed (scatter overwrites rows later)
    cudaMemcpyAsync(out_u, uE, Ue * sizeof(float), cudaMemcpyDeviceToDevice);
    cudaMemcpyAsync(out_i, iE, Ie * sizeof(float), cudaMemcpyDeviceToDevice);

    // h_all / t_all
    {
        int total = 2 * HBM * 8;
        gather_ht_kernel<<<(total + 255) / 256, 256>>>(
            mh, mt, (const float4*)ent, (float4*)out_h, (float4*)out_t, HBM);
    }
    // r_all + fused Rh : warp-per-slot, 8 slots per 256-thread block
    gather_r_rh_kernel<<<(HBM + 7) / 8, 256>>>(
        mr, mh, (const float4*)rel, ent, (float4*)out_r, HBM);

    // last-wins scatter resolution
    reset_winner_kernel<<<(B + 255) / 256, 256>>>(pos, B);
    vote_winner_kernel<<<(B + 255) / 256, 256>>>(pos, B);

    // hop computation + scatter (8 warps per block)
    ripple_kernel<<<(B + 7) / 8, 256>>>(pos, iE, out_t, W, out_i, B, nhop);
}

// round 3
// speedup vs baseline: 1.6142x; 1.0398x over previous
#include <cuda_runtime.h>

#define DD   32          // embedding dim D
#define MM   32          // memories per hop
#define LEAKY 0.2f

// scratch: Rh[slot*D + d], slot in [0, H*B*M)
__device__ float g_Rh[131072 * 32];

__device__ __forceinline__ float warpSum(float v) {
    #pragma unroll
    for (int off = 16; off; off >>= 1) v += __shfl_xor_sync(0xffffffffu, v, off);
    return v;
}
__device__ __forceinline__ float warpMax(float v) {
    #pragma unroll
    for (int off = 16; off; off >>= 1) v = fmaxf(v, __shfl_xor_sync(0xffffffffu, v, off));
    return v;
}

// ---------------------------------------------------------------------------
// MEGA kernel: blockIdx ranges select role.
//   [0, RB)          : r_all gather + fused Rh (warp-per-slot, 8 slots/block)
//   [RB, RB+HB)      : h_all / t_all gather (float4 granularity)
//   [RB+HB, ...)     : uEmbed + iEmbed contiguous copy (float4)
// r-blocks first: they are the long pole; the small work backfills the tail.
// ---------------------------------------------------------------------------
__global__ void __launch_bounds__(256) mega_kernel(
        const int*    __restrict__ pos,
        const int*    __restrict__ mh,
        const int*    __restrict__ mr,
        const int*    __restrict__ mt,
        const float4* __restrict__ uE4,
        const float4* __restrict__ iE4,
        const float4* __restrict__ ent4,
        const float4* __restrict__ rel4,
        float4* __restrict__ out_u4,      // out_u .. out_r contiguous
        float4* __restrict__ out_h4,
        float4* __restrict__ out_t4,
        float4* __restrict__ out_r4,
        int HBM, int RB, int HB, int Ue4, int Ie4) {
    __shared__ float4 sR4[8][256];        // used by r-blocks only (32KB)
    int blk = blockIdx.x;

    if (blk < RB) {
        // ---- r_all gather + Rh = R@h, one warp per slot ----
        int warp = threadIdx.x >> 5, lane = threadIdx.x & 31;
        int slot = blk * 8 + warp;
        if (slot >= HBM) return;

        int r = __ldg(&mr[slot]);
        const float4* src = rel4 + (size_t)r * 256;
        float4* dst = out_r4 + (size_t)slot * 256;
        float4* s = sR4[warp];

        float4 v[8];
        #pragma unroll
        for (int k = 0; k < 8; k++)       // 8 outstanding L2 loads per lane
            v[k] = __ldg(&src[k * 32 + lane]);

        int e = __ldg(&mh[slot]);
        float hval = __ldg(&((const float*)ent4)[(size_t)e * DD + lane]);

        #pragma unroll
        for (int k = 0; k < 8; k++) {
            __stcs(&dst[k * 32 + lane], v[k]);  // streaming: never re-read
            s[k * 32 + lane] = v[k];
        }
        __syncwarp();

        const float* sR = (const float*)s;
        float acc = 0.f;
        #pragma unroll
        for (int i = 0; i < DD; i++) {
            int ee = (i + lane) & (DD - 1);     // conflict-free rotation
            acc = fmaf(sR[lane * DD + ee],
                       __shfl_sync(0xffffffffu, hval, ee), acc);
        }
        g_Rh[(size_t)slot * DD + lane] = acc;
    } else if (blk < RB + HB) {
        // ---- h_all / t_all gather ----
        int tid = (blk - RB) * 256 + threadIdx.x;
        int N = HBM * 8;                  // 8 float4 per 32-float row
        if (tid < N) {
            int slot = tid >> 3, j = tid & 7;
            int e = __ldg(&mh[slot]);
            __stcs(&out_h4[slot * 8 + j], ent4[(size_t)e * 8 + j]);
        } else if (tid < 2 * N) {
            int t2 = tid - N;
            int slot = t2 >> 3, j = t2 & 7;
            int e = __ldg(&mt[slot]);
            float4 v = ent4[(size_t)e * 8 + j];
            v.x = v.x > 0.f ? v.x : LEAKY * v.x;
            v.y = v.y > 0.f ? v.y : LEAKY * v.y;
            v.z = v.z > 0.f ? v.z : LEAKY * v.z;
            v.w = v.w > 0.f ? v.w : LEAKY * v.w;
            out_t4[slot * 8 + j] = v;     // re-read by ripple: keep cacheable
        }
    } else {
        // ---- uEmbed + iEmbed copy (contiguous dst region) ----
        int j = (blk - RB - HB) * 256 + threadIdx.x;
        if (j < Ue4)
            __stcs(&out_u4[j], __ldg(&uE4[j]));
        else if (j < Ue4 + Ie4)
            out_u4[j] = __ldg(&iE4[j - Ue4]);   // iEmbed rows re-written by scatter
    }
}

// ---------------------------------------------------------------------------
// Hop loop: one warp per batch row b. lane = embedding dim d (= also m).
// Last-wins scatter resolved inline: warp scans pos[b+1..B) for a duplicate.
// ---------------------------------------------------------------------------
__global__ void ripple_kernel(const int* __restrict__ pos,
                              const float* __restrict__ iE,
                              const float* __restrict__ t_all,
                              const float* __restrict__ W,
                              float* __restrict__ out_i,
                              int B, int nhop) {
    __shared__ float sW[DD * DD];
    for (int i = threadIdx.x; i < DD * DD; i += blockDim.x) sW[i] = W[i];
    __syncthreads();
    int warp = threadIdx.x >> 5, lane = threadIdx.x & 31;
    int b = blockIdx.x * (blockDim.x >> 5) + warp;
    if (b >= B) return;
    int p = pos[b];

    // last-wins: if any later batch element maps to the same item, we lose.
    bool dup = false;
    for (int j = b + 1 + lane; j < B; j += 32)
        dup |= (pos[j] == p);
    if (__any_sync(0xffffffffu, dup)) return;

    float item = iE[(size_t)p * DD + lane];

    for (int hop = 0; hop < nhop; hop++) {
        const float* Rh = g_Rh + (size_t)(hop * B + b) * MM * DD;
        const float* tb = t_all + (size_t)(hop * B + b) * MM * DD;
        // logits[m] = sum_d Rh[m][d] * item[d]; kept on lane == m
        float myLogit = 0.f;
        #pragma unroll
        for (int m = 0; m < MM; m++) {
            float v = warpSum(Rh[m * DD + lane] * item);
            if (m == lane) myLogit = v;
        }
        // softmax across lanes (m)
        float mx = warpMax(myLogit);
        float ex = expf(myLogit - mx);
        float s = warpSum(ex);
        float prob = ex / s;
        // o[d] = sum_m prob[m] * t[m][d]
        float o = 0.f;
        #pragma unroll
        for (int m = 0; m < MM; m++) {
            float pm = __shfl_sync(0xffffffffu, prob, m);
            o = fmaf(pm, tb[m * DD + lane], o);
        }
        // item = (item + o) @ W.T  ->  out[d] = sum_e x[e] * W[d][e]
        float x = item + o;
        float ni = 0.f;
        #pragma unroll
        for (int e = 0; e < DD; e++) {
            int ee = (e + lane) & (DD - 1);
            ni = fmaf(__shfl_sync(0xffffffffu, x, ee), sW[lane * DD + ee], ni);
        }
        item = ni;
    }
    out_i[(size_t)p * DD + lane] = item;
}

// ---------------------------------------------------------------------------
extern "C" void kernel_launch(void* const* d_in, const int* in_sizes, int n_in,
                              void* d_out, int out_size) {
    const int*   pos = (const int*)d_in[0];
    const int*   mh  = (const int*)d_in[1];
    const int*   mr  = (const int*)d_in[2];
    const int*   mt  = (const int*)d_in[3];
    const float* uE  = (const float*)d_in[4];
    const float* iE  = (const float*)d_in[5];
    const float* ent = (const float*)d_in[6];
    const float* rel = (const float*)d_in[7];
    const float* W   = (const float*)d_in[8];
    float* out = (float*)d_out;

    const int B   = in_sizes[0];              // 2048
    const int HBM = in_sizes[1];              // H*B*M = 131072
    const int nhop = HBM / (B * MM);          // 2
    const size_t Ue = (size_t)in_sizes[4];    // USER*D floats
    const size_t Ie = (size_t)in_sizes[5];    // ITEM*D floats

    float* out_u = out;
    float* out_i = out_u + Ue;
    float* out_h = out_i + Ie;
    float* out_t = out_h + (size_t)HBM * DD;
    float* out_r = out_t + (size_t)HBM * DD;

    const int RB = (HBM + 7) / 8;                       // 16384 r-blocks
    const int HB = (2 * HBM * 8 + 255) / 256;           // 8192 ht-blocks
    const int Ue4 = (int)(Ue / 4), Ie4 = (int)(Ie / 4);
    const int CB = (Ue4 + Ie4 + 255) / 256;             // 6250 copy-blocks

    mega_kernel<<<RB + HB + CB, 256>>>(
        pos, mh, mr, mt,
        (const float4*)uE, (const float4*)iE,
        (const float4*)ent, (const float4*)rel,
        (float4*)out_u, (float4*)out_h, (float4*)out_t, (float4*)out_r,
        HBM, RB, HB, Ue4, Ie4);

    ripple_kernel<<<(B + 7) / 8, 256>>>(pos, iE, out_t, W, out_i, B, nhop);
}